// round 12
// baseline (speedup 1.0000x reference)
#include <cuda_runtime.h>

#define BS    64
#define SL    8192
#define EDIM  64
#define DDIM  64
#define VOCAB 1088
#define NVAL  64
#define NTILE 17
#define SPLIT 8
#define CHUNK (SL / SPLIT)          // 1024
#define EPT   4

// Scratch (no allocations allowed)
__device__ float g_M [EDIM * 128];   // M[e'][c] = 0.125 * sum_d Wq[d,e'] Wk[d,c]
__device__ float g_cb[128];          // cb[c]    = 0.125 * sum_d Wq_b[d]  Wk[d,c]
__device__ float g_EV[BS * NVAL];
__device__ float g_EK[BS * VOCAB];
__device__ float g_num[BS * NVAL];   // zero-init; reset by combining block
__device__ int   g_cnt[BS];          // zero-init; reset by combining block

// ---------------------------------------------------------------------------
// A0: batch-INDEPENDENT fused matrix M = 0.125*Wq^T*Wk and bias row cb.
// 65 blocks x 128 threads: block e' (0..63) computes row e'; block 64 does cb.
// Wk loads coalesced across lanes; one 64-FMA dot per thread.
// ---------------------------------------------------------------------------
__global__ __launch_bounds__(128) void prep_kernel(
    const float* __restrict__ Wk_w,   // (64, 128) row-major
    const float* __restrict__ Wq_w,   // (64, 64) row-major
    const float* __restrict__ Wq_b)
{
    const int ep  = blockIdx.x;       // 0..63 = M row, 64 = bias
    const int tid = threadIdx.x;      // c = tid

    __shared__ float wq[DDIM];
    if (tid < DDIM)
        wq[tid] = (ep < EDIM) ? Wq_w[(size_t)tid * EDIM + ep] : Wq_b[tid];
    __syncthreads();

    float acc = 0.f;
    #pragma unroll
    for (int d = 0; d < DDIM; d++)
        acc = fmaf(Wk_w[(size_t)d * 128 + tid], wq[d], acc);
    acc *= 0.125f;

    if (ep < EDIM) g_M[ep * 128 + tid] = acc;
    else           g_cb[tid] = acc;
}

// ---------------------------------------------------------------------------
// A1: EK (and EV from tile==0 blocks). grid = 64 batches x 17 tiles = 1088
// independent blocks, 128 threads. Per block: eq load -> GEMV through M
// (coalesced, L2-hot) -> staged-tile dot -> exp -> coalesced write.
// ---------------------------------------------------------------------------
__global__ __launch_bounds__(128) void ek_kernel(
    const int*   __restrict__ q,
    const float* __restrict__ embK)
{
    const int bid  = blockIdx.x;
    const int b    = bid / NTILE;
    const int tile = bid % NTILE;
    const int v0   = tile * 64;
    const int tid  = threadIdx.x;
    const int v    = tid & 63;
    const int h    = tid >> 6;

    __shared__ float eqs[EDIM];
    __shared__ float qks[EDIM];
    __shared__ float tl[64 * 65];     // padded: (v + c) % 32 banks
    __shared__ float part[128];
    __shared__ float pev[128];

    const int qb = q[b];              // same address per block -> broadcast
    if (tid < EDIM) eqs[tid] = embK[(size_t)qb * EDIM + tid];
    // Coalesced tile load (independent of eqs chain)
    {
        const float4* src = reinterpret_cast<const float4*>(embK + (size_t)v0 * EDIM);
        for (int i = tid; i < 1024; i += 128) {
            const float4 val = src[i];
            float* d = &tl[(i >> 4) * 65 + (i & 15) * 4];
            d[0] = val.x; d[1] = val.y; d[2] = val.z; d[3] = val.w;
        }
    }
    __syncthreads();

    // GEMV: Qk[v] partial over e' half h (M rows coalesced across lanes)
    {
        float acc = 0.f;
        #pragma unroll
        for (int i = 0; i < 32; i++)
            acc = fmaf(eqs[h * 32 + i], g_M[(h * 32 + i) * 128 + 64 + v], acc);
        part[tid] = acc;
    }
    if (tile == 0) {                  // EV GEMV (lo columns), block-uniform
        float a2 = 0.f;
        #pragma unroll
        for (int i = 0; i < 32; i++)
            a2 = fmaf(eqs[h * 32 + i], g_M[(h * 32 + i) * 128 + v], a2);
        pev[tid] = a2;
    }
    __syncthreads();

    if (tid < EDIM) qks[tid] = part[tid] + part[tid + 64] + g_cb[64 + tid];
    if (tile == 0 && tid < NVAL)
        g_EV[b * NVAL + tid] = __expf(pev[tid] + pev[tid + 64] + g_cb[tid]);
    __syncthreads();

    // Tile dot: EK[v0+v] = exp(embK[v0+v] . Qk)
    {
        float acc = 0.f;
        #pragma unroll
        for (int i = 0; i < 32; i++)
            acc = fmaf(tl[v * 65 + h * 32 + i], qks[h * 32 + i], acc);
        part[tid] = acc;
    }
    __syncthreads();

    if (tid < 64)
        g_EK[(size_t)b * VOCAB + v0 + tid] = __expf(part[tid] + part[tid + 64]);
}

// ---------------------------------------------------------------------------
// Kernel B: gather-histogram (byte-identical to R11: measured best structure).
// grid = 64 batches x 8 splits (512 blocks), 256 threads, 4 elems/thread.
// ---------------------------------------------------------------------------
__global__ __launch_bounds__(256) void attn_kernel(
    const int* __restrict__ x,
    float*     __restrict__ out)
{
    const int b    = blockIdx.x >> 3;
    const int sp   = blockIdx.x & 7;
    const int tid  = threadIdx.x;
    const int warp = tid >> 5;

    __shared__ float EKs[VOCAB];
    __shared__ float bins[8][NVAL];     // warp-replicated histograms
    __shared__ float num[NVAL];
    __shared__ float rcpZ;
    __shared__ int   lastFlag;

    // Prefetch index data first (DRAM) — overlaps table fill (L2)
    const int* kp = x + (size_t)b * 2 * SL + sp * CHUNK;
    const int* vp = kp + SL;
    const int4 k4 = __ldg(reinterpret_cast<const int4*>(kp) + tid);
    const int4 w4 = __ldg(reinterpret_cast<const int4*>(vp) + tid);

    // EK table fill (vectorized, from L2)
    {
        const float4* src = reinterpret_cast<const float4*>(g_EK + (size_t)b * VOCAB);
        float4* dst = reinterpret_cast<float4*>(EKs);
        for (int i = tid; i < VOCAB / 4; i += 256) dst[i] = src[i];
    }
    for (int i = tid; i < 8 * NVAL; i += 256) (&bins[0][0])[i] = 0.f;
    __syncthreads();

    const int kk[EPT] = {k4.x, k4.y, k4.z, k4.w};
    const int vv[EPT] = {w4.x - NVAL, w4.y - NVAL, w4.z - NVAL, w4.w - NVAL};

    #pragma unroll
    for (int i = 0; i < EPT; i++)
        atomicAdd(&bins[warp][vv[i]], EKs[kk[i]]);
    __syncthreads();

    // Block bins -> global accumulator (REDG)
    if (tid < NVAL) {
        float bsum = 0.f;
        #pragma unroll
        for (int w = 0; w < 8; w++) bsum += bins[w][tid];
        atomicAdd(&g_num[b * NVAL + tid], bsum);
    }
    __syncthreads();

    if (tid == 0) {
        __threadfence();                            // order REDGs before count
        const int old = atomicAdd(&g_cnt[b], 1);
        lastFlag = (old == SPLIT - 1) ? 1 : 0;
        __threadfence();                            // acquire
    }
    __syncthreads();

    if (lastFlag) {
        if (tid < NVAL) {
            volatile float* vnum = g_num + b * NVAL;
            num[tid] = vnum[tid] * g_EV[b * NVAL + tid];
        }
        __syncthreads();
        if (tid < 32) {
            float zz = num[tid] + num[tid + 32];
            #pragma unroll
            for (int o = 16; o > 0; o >>= 1) zz += __shfl_xor_sync(0xffffffffu, zz, o);
            if (tid == 0) rcpZ = __frcp_rn(zz);
        }
        __syncthreads();
        if (tid < NVAL) {
            out[b * NVAL + tid] = num[tid] * rcpZ;
            g_num[b * NVAL + tid] = 0.f;            // re-arm accumulator
        }
        __syncthreads();
        if (tid == 0) g_cnt[b] = 0;                 // re-arm counter
    }
}

// ---------------------------------------------------------------------------
// Inputs (metadata order): x(int32), q(int32), embK, Wk_w, Wk_b, Wq_w, Wq_b.
// Wk_b is softmax-invariant (constant per batch) and intentionally unused.
// ---------------------------------------------------------------------------
extern "C" void kernel_launch(void* const* d_in, const int* in_sizes, int n_in,
                              void* d_out, int out_size)
{
    const int*   x    = (const int*)  d_in[0];
    const int*   q    = (const int*)  d_in[1];
    const float* embK = (const float*)d_in[2];
    const float* Wk_w = (const float*)d_in[3];
    const float* Wq_w = (const float*)d_in[5];
    const float* Wq_b = (const float*)d_in[6];
    float* out = (float*)d_out;

    prep_kernel<<<EDIM + 1, 128>>>(Wk_w, Wq_w, Wq_b);
    ek_kernel<<<BS * NTILE, 128>>>(q, embK);
    attn_kernel<<<BS * SPLIT, 256>>>(x, out);
}